// round 13
// baseline (speedup 1.0000x reference)
#include <cuda_runtime.h>
#include <cuda_fp16.h>
#include <cstdint>

#define BB   32
#define NN   577
#define CC   768
#define HH   12
#define DD   64
#define MTOK (BB*NN)        // 18464
#define QKVN (3*CC)         // 2304

// Scratch (allocation-free rule: __device__ globals) — all fp16
__device__ __half g_Q[(size_t)BB*HH*NN*DD];
__device__ __half g_K[(size_t)BB*HH*NN*DD];
__device__ __half g_V[(size_t)BB*HH*NN*DD];
__device__ __half g_att[(size_t)MTOK*CC];
__device__ __half g_x[(size_t)MTOK*CC];
__device__ __half g_wqkv[(size_t)CC*QKVN];
__device__ __half g_wproj[(size_t)CC*CC];

// ---------------------------------------------------------------------------
// helpers
// ---------------------------------------------------------------------------
__device__ __forceinline__ uint32_t packh2(float a, float b) {
    __half2 h = __floats2half2_rn(a, b);
    return *(uint32_t*)&h;
}
__device__ __forceinline__ void ldsm4(uint32_t (&r)[4], uint32_t saddr) {
    asm volatile("ldmatrix.sync.aligned.m8n8.x4.shared.b16 {%0,%1,%2,%3}, [%4];"
        : "=r"(r[0]), "=r"(r[1]), "=r"(r[2]), "=r"(r[3]) : "r"(saddr));
}
__device__ __forceinline__ void ldsm4t(uint32_t (&r)[4], uint32_t saddr) {
    asm volatile("ldmatrix.sync.aligned.m8n8.x4.trans.shared.b16 {%0,%1,%2,%3}, [%4];"
        : "=r"(r[0]), "=r"(r[1]), "=r"(r[2]), "=r"(r[3]) : "r"(saddr));
}
__device__ __forceinline__ void mma_f16(float (&d)[4], const uint32_t (&a)[4],
                                        uint32_t b0, uint32_t b1,
                                        const float (&c)[4]) {
    asm volatile(
        "mma.sync.aligned.m16n8k16.row.col.f32.f16.f16.f32 "
        "{%0,%1,%2,%3}, {%4,%5,%6,%7}, {%8,%9}, {%10,%11,%12,%13};\n"
        : "=f"(d[0]), "=f"(d[1]), "=f"(d[2]), "=f"(d[3])
        : "r"(a[0]), "r"(a[1]), "r"(a[2]), "r"(a[3]),
          "r"(b0), "r"(b1),
          "f"(c[0]), "f"(c[1]), "f"(c[2]), "f"(c[3]));
}
__device__ __forceinline__ void cp16(uint32_t saddr, const void* gptr, int sz) {
    asm volatile("cp.async.cg.shared.global [%0], [%1], 16, %2;\n"
                 :: "r"(saddr), "l"(gptr), "r"(sz));
}
#define CP_COMMIT() asm volatile("cp.async.commit_group;\n")
template<int N> __device__ __forceinline__ void cp_wait() {
    asm volatile("cp.async.wait_group %0;\n" :: "n"(N));
}
__device__ __forceinline__ uint32_t smem_u32(const void* p) {
    uint32_t a;
    asm("{ .reg .u64 t; cvta.to.shared.u64 t, %1; cvt.u32.u64 %0, t; }"
        : "=r"(a) : "l"(p));
    return a;
}

// ---------------------------------------------------------------------------
// Pre-convert: fp32 -> fp16, all three tensors in ONE launch
// ---------------------------------------------------------------------------
__global__ void cvt_all_kernel(const float4* __restrict__ x,   uint2* __restrict__ gx,  int nx,
                               const float4* __restrict__ wq,  uint2* __restrict__ gwq, int nq,
                               const float4* __restrict__ wp,  uint2* __restrict__ gwp, int np)
{
    int i = blockIdx.x * blockDim.x + threadIdx.x;
    const float4* s;
    uint2* d;
    int j = i;
    if (j < nx) { s = x; d = gx; }
    else {
        j -= nx;
        if (j < nq) { s = wq; d = gwq; }
        else {
            j -= nq;
            if (j >= np) return;
            s = wp; d = gwp;
        }
    }
    float4 v = s[j];
    uint2 o;
    o.x = packh2(v.x, v.y);
    o.y = packh2(v.z, v.w);
    d[j] = o;
}

// ---------------------------------------------------------------------------
// fp16 GEMM mainloop: 256x128 block, 8 warps (4m x 2n, 64x64 each), BK=32,
// 3-stage cp.async, launch_bounds(256,2) -> 16 warps/SM.
// As [256][40] halves; Bs [32][136] halves.
// ---------------------------------------------------------------------------
#define AS_STR 40
#define BS_STR 136
#define AS_SZ  (256*AS_STR)              // 10240 halves
#define BS_SZ  (32*BS_STR)               // 4352 halves
#define STAGE_SZ (AS_SZ + BS_SZ)         // 14592 halves
#define GEMM_SMEM_BYTES (3*STAGE_SZ*2)   // 87552

__device__ __forceinline__ void gemm_cp(
    const __half* __restrict__ A, const __half* __restrict__ W,
    int M, int Kdim, int Nld, int m0, int n0,
    float (&acc)[4][8][4], __half* __restrict__ sm)
{
    const int tid  = threadIdx.x;
    const int lane = tid & 31;
    const int wid  = tid >> 5;
    const int wm   = (wid & 3) * 64;
    const int wn   = (wid >> 2) * 64;

    // staging coords (256 threads)
    const int arow = tid >> 2;           // 0..63 (rows arow + 64i), 4 chunks/row
    const int achk = (tid & 3) * 8;
    const int bkr  = tid >> 4;           // 0..15 (k rows bkr + 16i)
    const int bnc  = (tid & 15) * 8;

    const int lrow = (lane & 7) + ((lane >> 3) & 1) * 8;
    const int lcol = ((lane >> 4) & 1) * 8;

    const uint32_t s_base = smem_u32(sm);
    const int KT = Kdim / 32;

    auto issue = [&](int t, int buf) {
        int k0 = t * 32;
        uint32_t as = s_base + (uint32_t)(buf * STAGE_SZ) * 2u;
        uint32_t bs = as + AS_SZ * 2u;
        #pragma unroll
        for (int i = 0; i < 4; i++) {
            int row = arow + 64 * i;
            int gr  = m0 + row;
            int grs = (gr < M) ? gr : 0;
            cp16(as + (uint32_t)(row * AS_STR + achk) * 2u,
                 A + (size_t)grs * Kdim + k0 + achk, (gr < M) ? 16 : 0);
        }
        #pragma unroll
        for (int i = 0; i < 2; i++) {
            int kr = bkr + 16 * i;
            cp16(bs + (uint32_t)(kr * BS_STR + bnc) * 2u,
                 W + (size_t)(k0 + kr) * Nld + n0 + bnc, 16);
        }
    };

    issue(0, 0); CP_COMMIT();
    issue(1, 1); CP_COMMIT();

    for (int t = 0; t < KT; t++) {
        cp_wait<1>();
        __syncthreads();
        if (t + 2 < KT) issue(t + 2, (t + 2) % 3);
        CP_COMMIT();

        const uint32_t as = s_base + (uint32_t)((t % 3) * STAGE_SZ) * 2u;
        const uint32_t bs = as + AS_SZ * 2u;

        #pragma unroll
        for (int sub = 0; sub < 2; sub++) {
            uint32_t a[4][4];
            #pragma unroll
            for (int mt = 0; mt < 4; mt++)
                ldsm4(a[mt], as + (uint32_t)((wm + mt * 16 + lrow) * AS_STR
                                             + sub * 16 + lcol) * 2u);
            #pragma unroll
            for (int ntp = 0; ntp < 4; ntp++) {
                uint32_t bf[4];
                ldsm4t(bf, bs + (uint32_t)((sub * 16 + lrow) * BS_STR
                                           + wn + ntp * 16 + lcol) * 2u);
                #pragma unroll
                for (int mt = 0; mt < 4; mt++) {
                    mma_f16(acc[mt][2 * ntp],     a[mt], bf[0], bf[1], acc[mt][2 * ntp]);
                    mma_f16(acc[mt][2 * ntp + 1], a[mt], bf[2], bf[3], acc[mt][2 * ntp + 1]);
                }
            }
        }
    }
}

// ---------------------------------------------------------------------------
// Kernel 1: QKV GEMM + bias + RoPE + q-scale, scatter fp16 to [B,H,N,D].
// q-scale folds log2(e) so attention softmax can use raw exp2.
// Warp n-span = 64 = one head; RoPE pair (d, d^32) = acc[mt][nt^4].
// ---------------------------------------------------------------------------
#define QSCALE (0.125f * 1.4426950408889634f)

__global__ void __launch_bounds__(256, 2) qkv_kernel(
    const float* __restrict__ bias,
    const float* __restrict__ rsin, const float* __restrict__ rcos)
{
    extern __shared__ __half smh[];
    float acc[4][8][4] = {};
    const int m0 = blockIdx.y * 256;
    const int n0 = blockIdx.x * 128;

    gemm_cp(g_x, g_wqkv, MTOK, CC, QKVN, m0, n0, acc, smh);

    const int lane = threadIdx.x & 31;
    const int wid  = threadIdx.x >> 5;
    const int grp  = lane >> 2;
    const int tid4 = lane & 3;
    const int wm   = (wid & 3) * 64;
    const int wn   = (wid >> 2) * 64;

    const int which = n0 / CC;
    __half* dst = (which == 0) ? g_Q : ((which == 1) ? g_K : g_V);
    const int h = ((n0 + wn) % CC) / DD;
    const bool is_v = (which == 2);
    const bool is_q = (which == 0);

    #pragma unroll
    for (int nt = 0; nt < 8; nt++) {
        int c = n0 + wn + nt * 8 + 2 * tid4;
        float b0 = bias[c], b1 = bias[c + 1];
        #pragma unroll
        for (int mt = 0; mt < 4; mt++) {
            acc[mt][nt][0] += b0; acc[mt][nt][1] += b1;
            acc[mt][nt][2] += b0; acc[mt][nt][3] += b1;
        }
    }

    #pragma unroll
    for (int mt = 0; mt < 4; mt++) {
        #pragma unroll
        for (int rr = 0; rr < 2; rr++) {
            int m = m0 + wm + mt * 16 + grp + rr * 8;
            if (m >= MTOK) continue;
            int bb = m / NN;
            int n  = m - bb * NN;
            #pragma unroll
            for (int nt = 0; nt < 8; nt++) {
                int d0 = nt * 8 + 2 * tid4;
                float v0 = acc[mt][nt][2 * rr];
                float v1 = acc[mt][nt][2 * rr + 1];
                float o0 = v0, o1 = v1;
                if (!is_v && n > 0) {
                    float p0 = acc[mt][nt ^ 4][2 * rr];
                    float p1 = acc[mt][nt ^ 4][2 * rr + 1];
                    float sgn = (nt < 4) ? -1.f : 1.f;
                    float c0 = rcos[(n - 1) * DD + d0],     s0 = rsin[(n - 1) * DD + d0];
                    float c1 = rcos[(n - 1) * DD + d0 + 1], s1 = rsin[(n - 1) * DD + d0 + 1];
                    o0 = v0 * c0 + sgn * p0 * s0;
                    o1 = v1 * c1 + sgn * p1 * s1;
                }
                if (is_q) { o0 *= QSCALE; o1 *= QSCALE; }
                *(uint32_t*)(dst + (((size_t)bb * HH + h) * NN + n) * DD + d0) =
                    packh2(o0, o1);
            }
        }
    }
}

// ---------------------------------------------------------------------------
// Kernel 2: flash attention (round-12 proven config): 8 warps x 16 q-rows,
// 3-stage KV, one barrier per k-tile, no online max (exp2, log2e in q),
// l deferred. launch_bounds(256,2) = 16 warps/SM.
// ---------------------------------------------------------------------------
#define KV_STR 72
#define KV_STAGE (2*64*KV_STR)              // 9216 halves
#define QS_OFF (3*KV_STAGE)                 // 27648 halves
#define ATT_SMEM_HALVES (QS_OFF + 128*KV_STR)   // 36864
#define ATT_SMEM_BYTES  (ATT_SMEM_HALVES*2)     // 73728

__global__ void __launch_bounds__(256, 2) attn_kernel()
{
    extern __shared__ __half smh[];

    const int tid  = threadIdx.x;
    const int lane = tid & 31;
    const int wid  = tid >> 5;              // 0..7
    const int grp  = lane >> 2;
    const int tid4 = lane & 3;

    const int q0 = blockIdx.x * 128;
    const int bh = blockIdx.y;
    const int b = bh / HH, h = bh - b * HH;

    const __half* Qp = g_Q + (size_t)bh * NN * DD;
    const __half* Kp = g_K + (size_t)bh * NN * DD;
    const __half* Vp = g_V + (size_t)bh * NN * DD;

    const uint32_t s_base = smem_u32(smh);
    const uint32_t qs_u = s_base + QS_OFF * 2u;

    auto issueKV = [&](int t, int buf) {
        int kb = t * 64;
        uint32_t ks = s_base + (uint32_t)(buf * KV_STAGE) * 2u;
        uint32_t vs = ks + 64 * KV_STR * 2u;
        #pragma unroll
        for (int i = 0; i < 2; i++) {
            int c = tid + i * 256;
            int row = c >> 3, chk = (c & 7) * 8;
            int gr = kb + row;
            int grs = (gr < NN) ? gr : 0;
            int sz = (gr < NN) ? 16 : 0;
            cp16(ks + (uint32_t)(row * KV_STR + chk) * 2u, Kp + (size_t)grs * DD + chk, sz);
            cp16(vs + (uint32_t)(row * KV_STR + chk) * 2u, Vp + (size_t)grs * DD + chk, sz);
        }
    };

    // Q tile -> smem (group 0), then KV0, KV1
    #pragma unroll
    for (int i = 0; i < 4; i++) {
        int c = tid + i * 256;
        int row = c >> 3, chk = (c & 7) * 8;
        int gr = q0 + row;
        int grs = (gr < NN) ? gr : 0;
        cp16(qs_u + (uint32_t)(row * KV_STR + chk) * 2u,
             Qp + (size_t)grs * DD + chk, (gr < NN) ? 16 : 0);
    }
    CP_COMMIT();
    issueKV(0, 0); CP_COMMIT();
    issueKV(1, 1); CP_COMMIT();

    cp_wait<2>();                  // Q resident (KV0/KV1 in flight)
    __syncthreads();

    // Q fragments register-resident
    const int lrow = (lane & 7) + ((lane >> 3) & 1) * 8;
    const int lcol = ((lane >> 4) & 1) * 8;
    uint32_t aq[4][4];
    #pragma unroll
    for (int kb = 0; kb < 4; kb++)
        ldsm4(aq[kb],
              qs_u + (uint32_t)((wid * 16 + lrow) * KV_STR + kb * 16 + lcol) * 2u);

    const int krow = (lane & 7) + ((lane >> 4) & 1) * 8;
    const int kcol = ((lane >> 3) & 1) * 8;
    const int vrow = (lane & 7) + ((lane >> 3) & 1) * 8;
    const int vcol = ((lane >> 4) & 1) * 8;

    float o[8][4] = {};
    float l_st[2] = {0.f, 0.f};

    const int NKT = (NN + 63) / 64;   // 10
    for (int kt = 0; kt < NKT; kt++) {
        cp_wait<1>();
        __syncthreads();
        if (kt + 2 < NKT) issueKV(kt + 2, (kt + 2) % 3);
        CP_COMMIT();

        const uint32_t ks_u = s_base + (uint32_t)((kt % 3) * KV_STAGE) * 2u;
        const uint32_t vs_u = ks_u + 64 * KV_STR * 2u;
        const int kb_tok = kt * 64;

        float s[8][4] = {};
        #pragma unroll
        for (int kb = 0; kb < 4; kb++) {
            #pragma unroll
            for (int ntp = 0; ntp < 4; ntp++) {
                uint32_t bf[4];
                ldsm4(bf, ks_u + (uint32_t)((ntp * 16 + krow) * KV_STR + kb * 16 + kcol) * 2u);
                mma_f16(s[2 * ntp],     aq[kb], bf[0], bf[1], s[2 * ntp]);
                mma_f16(s[2 * ntp + 1], aq[kb], bf[2], bf[3], s[2 * ntp + 1]);
            }
        }

        if (kb_tok + 64 > NN) {
            #pragma unroll
            for (int nt = 0; nt < 8; nt++) {
                int c = kb_tok + nt * 8 + 2 * tid4;
                if (c >= NN)     { s[nt][0] = -1e30f; s[nt][2] = -1e30f; }
                if (c + 1 >= NN) { s[nt][1] = -1e30f; s[nt][3] = -1e30f; }
            }
        }

        #pragma unroll
        for (int nt = 0; nt < 8; nt++) {
            #pragma unroll
            for (int e = 0; e < 4; e++)
                s[nt][e] = exp2f(s[nt][e]);
            l_st[0] += s[nt][0] + s[nt][1];
            l_st[1] += s[nt][2] + s[nt][3];
        }

        #pragma unroll
        for (int kk = 0; kk < 4; kk++) {
            uint32_t ap[4];
            ap[0] = packh2(s[2 * kk][0],     s[2 * kk][1]);
            ap[1] = packh2(s[2 * kk][2],     s[2 * kk][3]);
            ap[2] = packh2(s[2 * kk + 1][0], s[2 * kk + 1][1]);
            ap[3] = packh2(s[2 * kk + 1][2], s[2 * kk + 1][3]);
            #pragma unroll
            for (int ntp = 0; ntp < 4; ntp++) {
                uint32_t bf[4];
                ldsm4t(bf, vs_u + (uint32_t)((kk * 16 + vrow) * KV_STR + ntp * 16 + vcol) * 2u);
                mma_f16(o[2 * ntp],     ap, bf[0], bf[1], o[2 * ntp]);
                mma_f16(o[2 * ntp + 1], ap, bf[2], bf[3], o[2 * ntp + 1]);
            }
        }
    }

    #pragma unroll
    for (int rr = 0; rr < 2; rr++) {
        l_st[rr] += __shfl_xor_sync(0xffffffffu, l_st[rr], 1);
        l_st[rr] += __shfl_xor_sync(0xffffffffu, l_st[rr], 2);
    }

    #pragma unroll
    for (int rr = 0; rr < 2; rr++) {
        int n = q0 + wid * 16 + grp + rr * 8;
        if (n >= NN) continue;
        float inv_l = 1.0f / l_st[rr];
        #pragma unroll
        for (int nt = 0; nt < 8; nt++) {
            int d0 = nt * 8 + 2 * tid4;
            *(uint32_t*)(g_att + ((size_t)b * NN + n) * CC + h * DD + d0) =
                packh2(o[nt][2 * rr] * inv_l, o[nt][2 * rr + 1] * inv_l);
        }
    }
}

// ---------------------------------------------------------------------------
// Kernel 3: output projection + bias -> d_out (fp32)
// ---------------------------------------------------------------------------
__global__ void __launch_bounds__(256, 2) proj_kernel(
    const float* __restrict__ bias, float* __restrict__ out)
{
    extern __shared__ __half smh[];
    float acc[4][8][4] = {};
    const int m0 = blockIdx.y * 256;
    const int n0 = blockIdx.x * 128;

    gemm_cp(g_att, g_wproj, MTOK, CC, CC, m0, n0, acc, smh);

    const int lane = threadIdx.x & 31;
    const int wid  = threadIdx.x >> 5;
    const int grp  = lane >> 2;
    const int tid4 = lane & 3;
    const int wm   = (wid & 3) * 64;
    const int wn   = (wid >> 2) * 64;

    #pragma unroll
    for (int mt = 0; mt < 4; mt++) {
        #pragma unroll
        for (int rr = 0; rr < 2; rr++) {
            int r = m0 + wm + mt * 16 + grp + rr * 8;
            if (r >= MTOK) continue;
            #pragma unroll
            for (int nt = 0; nt < 8; nt++) {
                int c = n0 + wn + nt * 8 + 2 * tid4;
                float2 ov = make_float2(acc[mt][nt][2 * rr] + bias[c],
                                        acc[mt][nt][2 * rr + 1] + bias[c + 1]);
                *(float2*)(out + (size_t)r * CC + c) = ov;
            }
        }
    }
}

// ---------------------------------------------------------------------------
extern "C" void kernel_launch(void* const* d_in, const int* in_sizes, int n_in,
                              void* d_out, int out_size)
{
    (void)in_sizes; (void)n_in; (void)out_size;
    const float* x      = (const float*)d_in[0];
    const float* w_qkv  = (const float*)d_in[1];
    const float* b_qkv  = (const float*)d_in[2];
    const float* w_proj = (const float*)d_in[3];
    const float* b_proj = (const float*)d_in[4];
    const float* rsin   = (const float*)d_in[5];
    const float* rcos   = (const float*)d_in[6];
    float* out = (float*)d_out;

    cudaFuncSetAttribute(qkv_kernel,  cudaFuncAttributeMaxDynamicSharedMemorySize, GEMM_SMEM_BYTES);
    cudaFuncSetAttribute(proj_kernel, cudaFuncAttributeMaxDynamicSharedMemorySize, GEMM_SMEM_BYTES);
    cudaFuncSetAttribute(attn_kernel, cudaFuncAttributeMaxDynamicSharedMemorySize, ATT_SMEM_BYTES);

    __half* gx;  cudaGetSymbolAddress((void**)&gx,  g_x);
    __half* gwq; cudaGetSymbolAddress((void**)&gwq, g_wqkv);
    __half* gwp; cudaGetSymbolAddress((void**)&gwp, g_wproj);

    int n4x = MTOK * CC / 4;
    int n4q = CC * QKVN / 4;
    int n4p = CC * CC / 4;
    int n4  = n4x + n4q + n4p;
    cvt_all_kernel<<<(n4 + 255) / 256, 256>>>(
        (const float4*)x,      (uint2*)gx,  n4x,
        (const float4*)w_qkv,  (uint2*)gwq, n4q,
        (const float4*)w_proj, (uint2*)gwp, n4p);

    dim3 g1(QKVN / 128, (MTOK + 255) / 256);     // 18 x 73
    qkv_kernel<<<g1, 256, GEMM_SMEM_BYTES>>>(b_qkv, rsin, rcos);

    dim3 g2((NN + 127) / 128, BB * HH);          // 5 x 384
    attn_kernel<<<g2, 256, ATT_SMEM_BYTES>>>();

    dim3 g3(CC / 128, (MTOK + 255) / 256);       // 6 x 73
    proj_kernel<<<g3, 256, GEMM_SMEM_BYTES>>>(b_proj, out);
}

// round 14
// speedup vs baseline: 2.1105x; 2.1105x over previous
#include <cuda_runtime.h>
#include <cuda_fp16.h>
#include <cstdint>

#define BB   32
#define NN   577
#define CC   768
#define HH   12
#define DD   64
#define MTOK (BB*NN)        // 18464
#define QKVN (3*CC)         // 2304

// Scratch (allocation-free rule: __device__ globals) — all fp16
__device__ __half g_Q[(size_t)BB*HH*NN*DD];
__device__ __half g_K[(size_t)BB*HH*NN*DD];
__device__ __half g_V[(size_t)BB*HH*NN*DD];
__device__ __half g_att[(size_t)MTOK*CC];
__device__ __half g_x[(size_t)MTOK*CC];
__device__ __half g_wqkv[(size_t)CC*QKVN];
__device__ __half g_wproj[(size_t)CC*CC];

// ---------------------------------------------------------------------------
// helpers
// ---------------------------------------------------------------------------
__device__ __forceinline__ uint32_t packh2(float a, float b) {
    __half2 h = __floats2half2_rn(a, b);
    return *(uint32_t*)&h;
}
__device__ __forceinline__ void ldsm4(uint32_t (&r)[4], uint32_t saddr) {
    asm volatile("ldmatrix.sync.aligned.m8n8.x4.shared.b16 {%0,%1,%2,%3}, [%4];"
        : "=r"(r[0]), "=r"(r[1]), "=r"(r[2]), "=r"(r[3]) : "r"(saddr));
}
__device__ __forceinline__ void ldsm4t(uint32_t (&r)[4], uint32_t saddr) {
    asm volatile("ldmatrix.sync.aligned.m8n8.x4.trans.shared.b16 {%0,%1,%2,%3}, [%4];"
        : "=r"(r[0]), "=r"(r[1]), "=r"(r[2]), "=r"(r[3]) : "r"(saddr));
}
__device__ __forceinline__ void mma_f16(float (&d)[4], const uint32_t (&a)[4],
                                        uint32_t b0, uint32_t b1,
                                        const float (&c)[4]) {
    asm volatile(
        "mma.sync.aligned.m16n8k16.row.col.f32.f16.f16.f32 "
        "{%0,%1,%2,%3}, {%4,%5,%6,%7}, {%8,%9}, {%10,%11,%12,%13};\n"
        : "=f"(d[0]), "=f"(d[1]), "=f"(d[2]), "=f"(d[3])
        : "r"(a[0]), "r"(a[1]), "r"(a[2]), "r"(a[3]),
          "r"(b0), "r"(b1),
          "f"(c[0]), "f"(c[1]), "f"(c[2]), "f"(c[3]));
}
__device__ __forceinline__ void cp16(uint32_t saddr, const void* gptr, int sz) {
    asm volatile("cp.async.cg.shared.global [%0], [%1], 16, %2;\n"
                 :: "r"(saddr), "l"(gptr), "r"(sz));
}
#define CP_COMMIT() asm volatile("cp.async.commit_group;\n")
template<int N> __device__ __forceinline__ void cp_wait() {
    asm volatile("cp.async.wait_group %0;\n" :: "n"(N));
}
__device__ __forceinline__ uint32_t smem_u32(const void* p) {
    uint32_t a;
    asm("{ .reg .u64 t; cvta.to.shared.u64 t, %1; cvt.u32.u64 %0, t; }"
        : "=r"(a) : "l"(p));
    return a;
}

// ---------------------------------------------------------------------------
// Pre-convert: fp32 -> fp16, all three tensors in ONE launch (512 threads)
// ---------------------------------------------------------------------------
__global__ void cvt_all_kernel(const float4* __restrict__ x,   uint2* __restrict__ gx,  int nx,
                               const float4* __restrict__ wq,  uint2* __restrict__ gwq, int nq,
                               const float4* __restrict__ wp,  uint2* __restrict__ gwp, int np)
{
    int i = blockIdx.x * blockDim.x + threadIdx.x;
    const float4* s;
    uint2* d;
    int j = i;
    if (j < nx) { s = x; d = gx; }
    else {
        j -= nx;
        if (j < nq) { s = wq; d = gwq; }
        else {
            j -= nq;
            if (j >= np) return;
            s = wp; d = gwp;
        }
    }
    float4 v = s[j];
    uint2 o;
    o.x = packh2(v.x, v.y);
    o.y = packh2(v.z, v.w);
    d[j] = o;
}

// ---------------------------------------------------------------------------
// fp16 GEMM mainloop (round-12 proven config): 128x128 block, 4 warps
// (64x64 each), BK=32, 3-stage cp.async, launch_bounds(128,3) = 12 warps/SM.
// NOTE: 64x64 warp tile requires ~168 regs; 3 CTAs of 128 thr is the max
// occupancy this tile supports (anything forcing <=128 regs spills: round 13).
// ---------------------------------------------------------------------------
#define AS_STR 40
#define BS_STR 136
#define AS_SZ  (128*AS_STR)
#define BS_SZ  (32*BS_STR)
#define STAGE_SZ (AS_SZ + BS_SZ)
#define GEMM_SMEM_BYTES (3*STAGE_SZ*2)  // 56832

__device__ __forceinline__ void gemm_cp(
    const __half* __restrict__ A, const __half* __restrict__ W,
    int M, int Kdim, int Nld, int m0, int n0,
    float (&acc)[4][8][4], __half* __restrict__ sm)
{
    const int tid  = threadIdx.x;
    const int lane = tid & 31;
    const int wid  = tid >> 5;
    const int wm   = (wid & 1) * 64;
    const int wn   = (wid >> 1) * 64;

    const int arow = tid >> 2;
    const int achk = (tid & 3) * 8;
    const int bkr  = tid >> 4;
    const int bnc  = (tid & 15) * 8;

    const int lrow = (lane & 7) + ((lane >> 3) & 1) * 8;
    const int lcol = ((lane >> 4) & 1) * 8;

    const uint32_t s_base = smem_u32(sm);
    const int KT = Kdim / 32;

    auto issue = [&](int t, int buf) {
        int k0 = t * 32;
        uint32_t as = s_base + (uint32_t)(buf * STAGE_SZ) * 2u;
        uint32_t bs = as + AS_SZ * 2u;
        #pragma unroll
        for (int i = 0; i < 4; i++) {
            int row = arow + 32 * i;
            int gr  = m0 + row;
            int grs = (gr < M) ? gr : 0;
            cp16(as + (uint32_t)(row * AS_STR + achk) * 2u,
                 A + (size_t)grs * Kdim + k0 + achk, (gr < M) ? 16 : 0);
        }
        #pragma unroll
        for (int i = 0; i < 4; i++) {
            int kr = bkr + 8 * i;
            cp16(bs + (uint32_t)(kr * BS_STR + bnc) * 2u,
                 W + (size_t)(k0 + kr) * Nld + n0 + bnc, 16);
        }
    };

    issue(0, 0); CP_COMMIT();
    issue(1, 1); CP_COMMIT();

    for (int t = 0; t < KT; t++) {
        cp_wait<1>();
        __syncthreads();
        if (t + 2 < KT) issue(t + 2, (t + 2) % 3);
        CP_COMMIT();

        const uint32_t as = s_base + (uint32_t)((t % 3) * STAGE_SZ) * 2u;
        const uint32_t bs = as + AS_SZ * 2u;

        #pragma unroll
        for (int sub = 0; sub < 2; sub++) {
            uint32_t a[4][4];
            #pragma unroll
            for (int mt = 0; mt < 4; mt++)
                ldsm4(a[mt], as + (uint32_t)((wm + mt * 16 + lrow) * AS_STR
                                             + sub * 16 + lcol) * 2u);
            #pragma unroll
            for (int ntp = 0; ntp < 4; ntp++) {
                uint32_t bf[4];
                ldsm4t(bf, bs + (uint32_t)((sub * 16 + lrow) * BS_STR
                                           + wn + ntp * 16 + lcol) * 2u);
                #pragma unroll
                for (int mt = 0; mt < 4; mt++) {
                    mma_f16(acc[mt][2 * ntp],     a[mt], bf[0], bf[1], acc[mt][2 * ntp]);
                    mma_f16(acc[mt][2 * ntp + 1], a[mt], bf[2], bf[3], acc[mt][2 * ntp + 1]);
                }
            }
        }
    }
}

// ---------------------------------------------------------------------------
// Kernel 1: QKV GEMM + bias + RoPE + q-scale, scatter fp16 to [B,H,N,D].
// q-scale folds log2(e) so attention softmax can use raw exp2.
// ---------------------------------------------------------------------------
#define QSCALE (0.125f * 1.4426950408889634f)

__global__ void __launch_bounds__(128, 3) qkv_kernel(
    const float* __restrict__ bias,
    const float* __restrict__ rsin, const float* __restrict__ rcos)
{
    extern __shared__ __half smh[];
    float acc[4][8][4] = {};
    const int m0 = blockIdx.y * 128;
    const int n0 = blockIdx.x * 128;

    gemm_cp(g_x, g_wqkv, MTOK, CC, QKVN, m0, n0, acc, smh);

    const int lane = threadIdx.x & 31;
    const int wid  = threadIdx.x >> 5;
    const int grp  = lane >> 2;
    const int tid4 = lane & 3;
    const int wm   = (wid & 1) * 64;
    const int wn   = (wid >> 1) * 64;

    const int which = n0 / CC;
    __half* dst = (which == 0) ? g_Q : ((which == 1) ? g_K : g_V);
    const int h = ((n0 + wn) % CC) / DD;
    const bool is_v = (which == 2);
    const bool is_q = (which == 0);

    #pragma unroll
    for (int nt = 0; nt < 8; nt++) {
        int c = n0 + wn + nt * 8 + 2 * tid4;
        float b0 = bias[c], b1 = bias[c + 1];
        #pragma unroll
        for (int mt = 0; mt < 4; mt++) {
            acc[mt][nt][0] += b0; acc[mt][nt][1] += b1;
            acc[mt][nt][2] += b0; acc[mt][nt][3] += b1;
        }
    }

    #pragma unroll
    for (int mt = 0; mt < 4; mt++) {
        #pragma unroll
        for (int rr = 0; rr < 2; rr++) {
            int m = m0 + wm + mt * 16 + grp + rr * 8;
            if (m >= MTOK) continue;
            int bb = m / NN;
            int n  = m - bb * NN;
            #pragma unroll
            for (int nt = 0; nt < 8; nt++) {
                int d0 = nt * 8 + 2 * tid4;
                float v0 = acc[mt][nt][2 * rr];
                float v1 = acc[mt][nt][2 * rr + 1];
                float o0 = v0, o1 = v1;
                if (!is_v && n > 0) {
                    float p0 = acc[mt][nt ^ 4][2 * rr];
                    float p1 = acc[mt][nt ^ 4][2 * rr + 1];
                    float sgn = (nt < 4) ? -1.f : 1.f;
                    float c0 = rcos[(n - 1) * DD + d0],     s0 = rsin[(n - 1) * DD + d0];
                    float c1 = rcos[(n - 1) * DD + d0 + 1], s1 = rsin[(n - 1) * DD + d0 + 1];
                    o0 = v0 * c0 + sgn * p0 * s0;
                    o1 = v1 * c1 + sgn * p1 * s1;
                }
                if (is_q) { o0 *= QSCALE; o1 *= QSCALE; }
                *(uint32_t*)(dst + (((size_t)bb * HH + h) * NN + n) * DD + d0) =
                    packh2(o0, o1);
            }
        }
    }
}

// ---------------------------------------------------------------------------
// Kernel 2: flash attention (round-12 proven config): 8 warps x 16 q-rows,
// 3-stage KV, one barrier per k-tile, no online max (exp2, log2e in q),
// l deferred. launch_bounds(256,2) = 16 warps/SM. Last (masked) tile peeled.
// ---------------------------------------------------------------------------
#define KV_STR 72
#define KV_STAGE (2*64*KV_STR)              // 9216 halves
#define QS_OFF (3*KV_STAGE)                 // 27648 halves
#define ATT_SMEM_HALVES (QS_OFF + 128*KV_STR)   // 36864
#define ATT_SMEM_BYTES  (ATT_SMEM_HALVES*2)     // 73728

__global__ void __launch_bounds__(256, 2) attn_kernel()
{
    extern __shared__ __half smh[];

    const int tid  = threadIdx.x;
    const int lane = tid & 31;
    const int wid  = tid >> 5;              // 0..7
    const int grp  = lane >> 2;
    const int tid4 = lane & 3;

    const int q0 = blockIdx.x * 128;
    const int bh = blockIdx.y;
    const int b = bh / HH, h = bh - b * HH;

    const __half* Qp = g_Q + (size_t)bh * NN * DD;
    const __half* Kp = g_K + (size_t)bh * NN * DD;
    const __half* Vp = g_V + (size_t)bh * NN * DD;

    const uint32_t s_base = smem_u32(smh);
    const uint32_t qs_u = s_base + QS_OFF * 2u;

    auto issueKV = [&](int t, int buf) {
        int kb = t * 64;
        uint32_t ks = s_base + (uint32_t)(buf * KV_STAGE) * 2u;
        uint32_t vs = ks + 64 * KV_STR * 2u;
        #pragma unroll
        for (int i = 0; i < 2; i++) {
            int c = tid + i * 256;
            int row = c >> 3, chk = (c & 7) * 8;
            int gr = kb + row;
            int grs = (gr < NN) ? gr : 0;
            int sz = (gr < NN) ? 16 : 0;
            cp16(ks + (uint32_t)(row * KV_STR + chk) * 2u, Kp + (size_t)grs * DD + chk, sz);
            cp16(vs + (uint32_t)(row * KV_STR + chk) * 2u, Vp + (size_t)grs * DD + chk, sz);
        }
    };

    // Q tile -> smem (group 0), then KV0, KV1
    #pragma unroll
    for (int i = 0; i < 4; i++) {
        int c = tid + i * 256;
        int row = c >> 3, chk = (c & 7) * 8;
        int gr = q0 + row;
        int grs = (gr < NN) ? gr : 0;
        cp16(qs_u + (uint32_t)(row * KV_STR + chk) * 2u,
             Qp + (size_t)grs * DD + chk, (gr < NN) ? 16 : 0);
    }
    CP_COMMIT();
    issueKV(0, 0); CP_COMMIT();
    issueKV(1, 1); CP_COMMIT();

    cp_wait<2>();                  // Q resident (KV0/KV1 in flight)
    __syncthreads();

    // Q fragments register-resident
    const int lrow = (lane & 7) + ((lane >> 3) & 1) * 8;
    const int lcol = ((lane >> 4) & 1) * 8;
    uint32_t aq[4][4];
    #pragma unroll
    for (int kb = 0; kb < 4; kb++)
        ldsm4(aq[kb],
              qs_u + (uint32_t)((wid * 16 + lrow) * KV_STR + kb * 16 + lcol) * 2u);

    const int krow = (lane & 7) + ((lane >> 4) & 1) * 8;
    const int kcol = ((lane >> 3) & 1) * 8;
    const int vrow = (lane & 7) + ((lane >> 3) & 1) * 8;
    const int vcol = ((lane >> 4) & 1) * 8;

    float o[8][4] = {};
    float l_st[2] = {0.f, 0.f};

    const int NKT = (NN + 63) / 64;   // 10; tiles 0..NKT-2 full, last masked

    // one k-tile body; MASKED=true only for the peeled last tile
    auto tile_body = [&](int kt, bool masked) {
        cp_wait<1>();
        __syncthreads();
        if (kt + 2 < NKT) issueKV(kt + 2, (kt + 2) % 3);
        CP_COMMIT();

        const uint32_t ks_u = s_base + (uint32_t)((kt % 3) * KV_STAGE) * 2u;
        const uint32_t vs_u = ks_u + 64 * KV_STR * 2u;

        float s[8][4] = {};
        #pragma unroll
        for (int kb = 0; kb < 4; kb++) {
            #pragma unroll
            for (int ntp = 0; ntp < 4; ntp++) {
                uint32_t bf[4];
                ldsm4(bf, ks_u + (uint32_t)((ntp * 16 + krow) * KV_STR + kb * 16 + kcol) * 2u);
                mma_f16(s[2 * ntp],     aq[kb], bf[0], bf[1], s[2 * ntp]);
                mma_f16(s[2 * ntp + 1], aq[kb], bf[2], bf[3], s[2 * ntp + 1]);
            }
        }

        if (masked) {
            const int kb_tok = kt * 64;
            #pragma unroll
            for (int nt = 0; nt < 8; nt++) {
                int c = kb_tok + nt * 8 + 2 * tid4;
                if (c >= NN)     { s[nt][0] = -1e30f; s[nt][2] = -1e30f; }
                if (c + 1 >= NN) { s[nt][1] = -1e30f; s[nt][3] = -1e30f; }
            }
        }

        #pragma unroll
        for (int nt = 0; nt < 8; nt++) {
            #pragma unroll
            for (int e = 0; e < 4; e++)
                s[nt][e] = exp2f(s[nt][e]);
            l_st[0] += s[nt][0] + s[nt][1];
            l_st[1] += s[nt][2] + s[nt][3];
        }

        #pragma unroll
        for (int kk = 0; kk < 4; kk++) {
            uint32_t ap[4];
            ap[0] = packh2(s[2 * kk][0],     s[2 * kk][1]);
            ap[1] = packh2(s[2 * kk][2],     s[2 * kk][3]);
            ap[2] = packh2(s[2 * kk + 1][0], s[2 * kk + 1][1]);
            ap[3] = packh2(s[2 * kk + 1][2], s[2 * kk + 1][3]);
            #pragma unroll
            for (int ntp = 0; ntp < 4; ntp++) {
                uint32_t bf[4];
                ldsm4t(bf, vs_u + (uint32_t)((kk * 16 + vrow) * KV_STR + ntp * 16 + vcol) * 2u);
                mma_f16(o[2 * ntp],     ap, bf[0], bf[1], o[2 * ntp]);
                mma_f16(o[2 * ntp + 1], ap, bf[2], bf[3], o[2 * ntp + 1]);
            }
        }
    };

    for (int kt = 0; kt < NKT - 1; kt++)
        tile_body(kt, false);
    tile_body(NKT - 1, true);        // peeled masked tile

    #pragma unroll
    for (int rr = 0; rr < 2; rr++) {
        l_st[rr] += __shfl_xor_sync(0xffffffffu, l_st[rr], 1);
        l_st[rr] += __shfl_xor_sync(0xffffffffu, l_st[rr], 2);
    }

    #pragma unroll
    for (int rr = 0; rr < 2; rr++) {
        int n = q0 + wid * 16 + grp + rr * 8;
        if (n >= NN) continue;
        float inv_l = 1.0f / l_st[rr];
        #pragma unroll
        for (int nt = 0; nt < 8; nt++) {
            int d0 = nt * 8 + 2 * tid4;
            *(uint32_t*)(g_att + ((size_t)b * NN + n) * CC + h * DD + d0) =
                packh2(o[nt][2 * rr] * inv_l, o[nt][2 * rr + 1] * inv_l);
        }
    }
}

// ---------------------------------------------------------------------------
// Kernel 3: output projection + bias -> d_out (fp32)
// ---------------------------------------------------------------------------
__global__ void __launch_bounds__(128, 3) proj_kernel(
    const float* __restrict__ bias, float* __restrict__ out)
{
    extern __shared__ __half smh[];
    float acc[4][8][4] = {};
    const int m0 = blockIdx.y * 128;
    const int n0 = blockIdx.x * 128;

    gemm_cp(g_att, g_wproj, MTOK, CC, CC, m0, n0, acc, smh);

    const int lane = threadIdx.x & 31;
    const int wid  = threadIdx.x >> 5;
    const int grp  = lane >> 2;
    const int tid4 = lane & 3;
    const int wm   = (wid & 1) * 64;
    const int wn   = (wid >> 1) * 64;

    #pragma unroll
    for (int mt = 0; mt < 4; mt++) {
        #pragma unroll
        for (int rr = 0; rr < 2; rr++) {
            int r = m0 + wm + mt * 16 + grp + rr * 8;
            if (r >= MTOK) continue;
            #pragma unroll
            for (int nt = 0; nt < 8; nt++) {
                int c = n0 + wn + nt * 8 + 2 * tid4;
                float2 ov = make_float2(acc[mt][nt][2 * rr] + bias[c],
                                        acc[mt][nt][2 * rr + 1] + bias[c + 1]);
                *(float2*)(out + (size_t)r * CC + c) = ov;
            }
        }
    }
}

// ---------------------------------------------------------------------------
extern "C" void kernel_launch(void* const* d_in, const int* in_sizes, int n_in,
                              void* d_out, int out_size)
{
    (void)in_sizes; (void)n_in; (void)out_size;
    const float* x      = (const float*)d_in[0];
    const float* w_qkv  = (const float*)d_in[1];
    const float* b_qkv  = (const float*)d_in[2];
    const float* w_proj = (const float*)d_in[3];
    const float* b_proj = (const float*)d_in[4];
    const float* rsin   = (const float*)d_in[5];
    const float* rcos   = (const float*)d_in[6];
    float* out = (float*)d_out;

    cudaFuncSetAttribute(qkv_kernel,  cudaFuncAttributeMaxDynamicSharedMemorySize, GEMM_SMEM_BYTES);
    cudaFuncSetAttribute(proj_kernel, cudaFuncAttributeMaxDynamicSharedMemorySize, GEMM_SMEM_BYTES);
    cudaFuncSetAttribute(attn_kernel, cudaFuncAttributeMaxDynamicSharedMemorySize, ATT_SMEM_BYTES);

    __half* gx;  cudaGetSymbolAddress((void**)&gx,  g_x);
    __half* gwq; cudaGetSymbolAddress((void**)&gwq, g_wqkv);
    __half* gwp; cudaGetSymbolAddress((void**)&gwp, g_wproj);

    int n4x = MTOK * CC / 4;
    int n4q = CC * QKVN / 4;
    int n4p = CC * CC / 4;
    int n4  = n4x + n4q + n4p;
    cvt_all_kernel<<<(n4 + 511) / 512, 512>>>(
        (const float4*)x,      (uint2*)gx,  n4x,
        (const float4*)w_qkv,  (uint2*)gwq, n4q,
        (const float4*)w_proj, (uint2*)gwp, n4p);

    dim3 g1(QKVN / 128, (MTOK + 127) / 128);     // 18 x 145
    qkv_kernel<<<g1, 128, GEMM_SMEM_BYTES>>>(b_qkv, rsin, rcos);

    dim3 g2((NN + 127) / 128, BB * HH);          // 5 x 384
    attn_kernel<<<g2, 256, ATT_SMEM_BYTES>>>();

    dim3 g3(CC / 128, (MTOK + 127) / 128);       // 6 x 145
    proj_kernel<<<g3, 128, GEMM_SMEM_BYTES>>>(b_proj, out);
}

// round 15
// speedup vs baseline: 2.1612x; 1.0240x over previous
#include <cuda_runtime.h>
#include <cuda_fp16.h>
#include <cstdint>

#define BB   32
#define NN   577
#define CC   768
#define HH   12
#define DD   64
#define MTOK (BB*NN)        // 18464
#define QKVN (3*CC)         // 2304

// Scratch (allocation-free rule: __device__ globals) — all fp16
__device__ __half g_Q[(size_t)BB*HH*NN*DD];
__device__ __half g_K[(size_t)BB*HH*NN*DD];
__device__ __half g_V[(size_t)BB*HH*NN*DD];
__device__ __half g_att[(size_t)MTOK*CC];
__device__ __half g_x[(size_t)MTOK*CC];
__device__ __half g_wqkv[(size_t)CC*QKVN];
__device__ __half g_wproj[(size_t)CC*CC];

// ---------------------------------------------------------------------------
// helpers
// ---------------------------------------------------------------------------
__device__ __forceinline__ uint32_t packh2(float a, float b) {
    __half2 h = __floats2half2_rn(a, b);
    return *(uint32_t*)&h;
}
__device__ __forceinline__ float ex2(float x) {
    float r;
    asm("ex2.approx.ftz.f32 %0, %1;" : "=f"(r) : "f"(x));
    return r;
}
__device__ __forceinline__ void ldsm4(uint32_t (&r)[4], uint32_t saddr) {
    asm volatile("ldmatrix.sync.aligned.m8n8.x4.shared.b16 {%0,%1,%2,%3}, [%4];"
        : "=r"(r[0]), "=r"(r[1]), "=r"(r[2]), "=r"(r[3]) : "r"(saddr));
}
__device__ __forceinline__ void ldsm4t(uint32_t (&r)[4], uint32_t saddr) {
    asm volatile("ldmatrix.sync.aligned.m8n8.x4.trans.shared.b16 {%0,%1,%2,%3}, [%4];"
        : "=r"(r[0]), "=r"(r[1]), "=r"(r[2]), "=r"(r[3]) : "r"(saddr));
}
__device__ __forceinline__ void mma_f16(float (&d)[4], const uint32_t (&a)[4],
                                        uint32_t b0, uint32_t b1,
                                        const float (&c)[4]) {
    asm volatile(
        "mma.sync.aligned.m16n8k16.row.col.f32.f16.f16.f32 "
        "{%0,%1,%2,%3}, {%4,%5,%6,%7}, {%8,%9}, {%10,%11,%12,%13};\n"
        : "=f"(d[0]), "=f"(d[1]), "=f"(d[2]), "=f"(d[3])
        : "r"(a[0]), "r"(a[1]), "r"(a[2]), "r"(a[3]),
          "r"(b0), "r"(b1),
          "f"(c[0]), "f"(c[1]), "f"(c[2]), "f"(c[3]));
}
__device__ __forceinline__ void cp16(uint32_t saddr, const void* gptr, int sz) {
    asm volatile("cp.async.cg.shared.global [%0], [%1], 16, %2;\n"
                 :: "r"(saddr), "l"(gptr), "r"(sz));
}
#define CP_COMMIT() asm volatile("cp.async.commit_group;\n")
template<int N> __device__ __forceinline__ void cp_wait() {
    asm volatile("cp.async.wait_group %0;\n" :: "n"(N));
}
__device__ __forceinline__ uint32_t smem_u32(const void* p) {
    uint32_t a;
    asm("{ .reg .u64 t; cvta.to.shared.u64 t, %1; cvt.u32.u64 %0, t; }"
        : "=r"(a) : "l"(p));
    return a;
}

// ---------------------------------------------------------------------------
// Pre-convert: fp32 -> fp16, all three tensors in ONE launch (512 threads)
// ---------------------------------------------------------------------------
__global__ void cvt_all_kernel(const float4* __restrict__ x,   uint2* __restrict__ gx,  int nx,
                               const float4* __restrict__ wq,  uint2* __restrict__ gwq, int nq,
                               const float4* __restrict__ wp,  uint2* __restrict__ gwp, int np)
{
    int i = blockIdx.x * blockDim.x + threadIdx.x;
    const float4* s;
    uint2* d;
    int j = i;
    if (j < nx) { s = x; d = gx; }
    else {
        j -= nx;
        if (j < nq) { s = wq; d = gwq; }
        else {
            j -= nq;
            if (j >= np) return;
            s = wp; d = gwp;
        }
    }
    float4 v = s[j];
    uint2 o;
    o.x = packh2(v.x, v.y);
    o.y = packh2(v.z, v.w);
    d[j] = o;
}

// ---------------------------------------------------------------------------
// fp16 GEMM mainloop (proven config): 128x128 block, 4 warps (64x64 each),
// BK=32, 3-stage cp.async, launch_bounds(128,3) = 12 warps/SM.
// NOTE: 64x64 warp tile requires ~168 regs; 3 CTAs of 128 thr is the max
// occupancy this tile supports (anything forcing <=128 regs spills: round 13).
// ---------------------------------------------------------------------------
#define AS_STR 40
#define BS_STR 136
#define AS_SZ  (128*AS_STR)
#define BS_SZ  (32*BS_STR)
#define STAGE_SZ (AS_SZ + BS_SZ)
#define GEMM_SMEM_BYTES (3*STAGE_SZ*2)  // 56832

__device__ __forceinline__ void gemm_cp(
    const __half* __restrict__ A, const __half* __restrict__ W,
    int M, int Kdim, int Nld, int m0, int n0,
    float (&acc)[4][8][4], __half* __restrict__ sm)
{
    const int tid  = threadIdx.x;
    const int lane = tid & 31;
    const int wid  = tid >> 5;
    const int wm   = (wid & 1) * 64;
    const int wn   = (wid >> 1) * 64;

    const int arow = tid >> 2;
    const int achk = (tid & 3) * 8;
    const int bkr  = tid >> 4;
    const int bnc  = (tid & 15) * 8;

    const int lrow = (lane & 7) + ((lane >> 3) & 1) * 8;
    const int lcol = ((lane >> 4) & 1) * 8;

    const uint32_t s_base = smem_u32(sm);
    const int KT = Kdim / 32;

    auto issue = [&](int t, int buf) {
        int k0 = t * 32;
        uint32_t as = s_base + (uint32_t)(buf * STAGE_SZ) * 2u;
        uint32_t bs = as + AS_SZ * 2u;
        #pragma unroll
        for (int i = 0; i < 4; i++) {
            int row = arow + 32 * i;
            int gr  = m0 + row;
            int grs = (gr < M) ? gr : 0;
            cp16(as + (uint32_t)(row * AS_STR + achk) * 2u,
                 A + (size_t)grs * Kdim + k0 + achk, (gr < M) ? 16 : 0);
        }
        #pragma unroll
        for (int i = 0; i < 4; i++) {
            int kr = bkr + 8 * i;
            cp16(bs + (uint32_t)(kr * BS_STR + bnc) * 2u,
                 W + (size_t)(k0 + kr) * Nld + n0 + bnc, 16);
        }
    };

    issue(0, 0); CP_COMMIT();
    issue(1, 1); CP_COMMIT();

    for (int t = 0; t < KT; t++) {
        cp_wait<1>();
        __syncthreads();
        if (t + 2 < KT) issue(t + 2, (t + 2) % 3);
        CP_COMMIT();

        const uint32_t as = s_base + (uint32_t)((t % 3) * STAGE_SZ) * 2u;
        const uint32_t bs = as + AS_SZ * 2u;

        #pragma unroll
        for (int sub = 0; sub < 2; sub++) {
            uint32_t a[4][4];
            #pragma unroll
            for (int mt = 0; mt < 4; mt++)
                ldsm4(a[mt], as + (uint32_t)((wm + mt * 16 + lrow) * AS_STR
                                             + sub * 16 + lcol) * 2u);
            #pragma unroll
            for (int ntp = 0; ntp < 4; ntp++) {
                uint32_t bf[4];
                ldsm4t(bf, bs + (uint32_t)((sub * 16 + lrow) * BS_STR
                                           + wn + ntp * 16 + lcol) * 2u);
                #pragma unroll
                for (int mt = 0; mt < 4; mt++) {
                    mma_f16(acc[mt][2 * ntp],     a[mt], bf[0], bf[1], acc[mt][2 * ntp]);
                    mma_f16(acc[mt][2 * ntp + 1], a[mt], bf[2], bf[3], acc[mt][2 * ntp + 1]);
                }
            }
        }
    }
}

// ---------------------------------------------------------------------------
// Kernel 1: QKV GEMM + bias + RoPE + q-scale, scatter fp16 to [B,H,N,D].
// q-scale folds log2(e) so attention softmax can use raw exp2.
// ---------------------------------------------------------------------------
#define QSCALE (0.125f * 1.4426950408889634f)

__global__ void __launch_bounds__(128, 3) qkv_kernel(
    const float* __restrict__ bias,
    const float* __restrict__ rsin, const float* __restrict__ rcos)
{
    extern __shared__ __half smh[];
    float acc[4][8][4] = {};
    const int m0 = blockIdx.y * 128;
    const int n0 = blockIdx.x * 128;

    gemm_cp(g_x, g_wqkv, MTOK, CC, QKVN, m0, n0, acc, smh);

    const int lane = threadIdx.x & 31;
    const int wid  = threadIdx.x >> 5;
    const int grp  = lane >> 2;
    const int tid4 = lane & 3;
    const int wm   = (wid & 1) * 64;
    const int wn   = (wid >> 1) * 64;

    const int which = n0 / CC;
    __half* dst = (which == 0) ? g_Q : ((which == 1) ? g_K : g_V);
    const int h = ((n0 + wn) % CC) / DD;
    const bool is_v = (which == 2);
    const bool is_q = (which == 0);

    #pragma unroll
    for (int nt = 0; nt < 8; nt++) {
        int c = n0 + wn + nt * 8 + 2 * tid4;
        float b0 = bias[c], b1 = bias[c + 1];
        #pragma unroll
        for (int mt = 0; mt < 4; mt++) {
            acc[mt][nt][0] += b0; acc[mt][nt][1] += b1;
            acc[mt][nt][2] += b0; acc[mt][nt][3] += b1;
        }
    }

    #pragma unroll
    for (int mt = 0; mt < 4; mt++) {
        #pragma unroll
        for (int rr = 0; rr < 2; rr++) {
            int m = m0 + wm + mt * 16 + grp + rr * 8;
            if (m >= MTOK) continue;
            int bb = m / NN;
            int n  = m - bb * NN;
            #pragma unroll
            for (int nt = 0; nt < 8; nt++) {
                int d0 = nt * 8 + 2 * tid4;
                float v0 = acc[mt][nt][2 * rr];
                float v1 = acc[mt][nt][2 * rr + 1];
                float o0 = v0, o1 = v1;
                if (!is_v && n > 0) {
                    float p0 = acc[mt][nt ^ 4][2 * rr];
                    float p1 = acc[mt][nt ^ 4][2 * rr + 1];
                    float sgn = (nt < 4) ? -1.f : 1.f;
                    // vectorized table loads (d0 even -> 8B aligned)
                    float2 cs = *(const float2*)(rcos + (size_t)(n - 1) * DD + d0);
                    float2 sn = *(const float2*)(rsin + (size_t)(n - 1) * DD + d0);
                    o0 = v0 * cs.x + sgn * p0 * sn.x;
                    o1 = v1 * cs.y + sgn * p1 * sn.y;
                }
                if (is_q) { o0 *= QSCALE; o1 *= QSCALE; }
                *(uint32_t*)(dst + (((size_t)bb * HH + h) * NN + n) * DD + d0) =
                    packh2(o0, o1);
            }
        }
    }
}

// ---------------------------------------------------------------------------
// Kernel 2: flash attention (proven config): 8 warps x 16 q-rows, 3-stage KV,
// one barrier per k-tile, no online max (raw ex2, log2e folded into q),
// l deferred, masked last tile peeled. launch_bounds(256,2) = 16 warps/SM.
// ---------------------------------------------------------------------------
#define KV_STR 72
#define KV_STAGE (2*64*KV_STR)              // 9216 halves
#define QS_OFF (3*KV_STAGE)                 // 27648 halves
#define ATT_SMEM_HALVES (QS_OFF + 128*KV_STR)   // 36864
#define ATT_SMEM_BYTES  (ATT_SMEM_HALVES*2)     // 73728

__global__ void __launch_bounds__(256, 2) attn_kernel()
{
    extern __shared__ __half smh[];

    const int tid  = threadIdx.x;
    const int lane = tid & 31;
    const int wid  = tid >> 5;              // 0..7
    const int grp  = lane >> 2;
    const int tid4 = lane & 3;

    const int q0 = blockIdx.x * 128;
    const int bh = blockIdx.y;
    const int b = bh / HH, h = bh - b * HH;

    const __half* Qp = g_Q + (size_t)bh * NN * DD;
    const __half* Kp = g_K + (size_t)bh * NN * DD;
    const __half* Vp = g_V + (size_t)bh * NN * DD;

    const uint32_t s_base = smem_u32(smh);
    const uint32_t qs_u = s_base + QS_OFF * 2u;

    auto issueKV = [&](int t, int buf) {
        int kb = t * 64;
        uint32_t ks = s_base + (uint32_t)(buf * KV_STAGE) * 2u;
        uint32_t vs = ks + 64 * KV_STR * 2u;
        #pragma unroll
        for (int i = 0; i < 2; i++) {
            int c = tid + i * 256;
            int row = c >> 3, chk = (c & 7) * 8;
            int gr = kb + row;
            int grs = (gr < NN) ? gr : 0;
            int sz = (gr < NN) ? 16 : 0;
            cp16(ks + (uint32_t)(row * KV_STR + chk) * 2u, Kp + (size_t)grs * DD + chk, sz);
            cp16(vs + (uint32_t)(row * KV_STR + chk) * 2u, Vp + (size_t)grs * DD + chk, sz);
        }
    };

    // Q tile -> smem (group 0), then KV0, KV1
    #pragma unroll
    for (int i = 0; i < 4; i++) {
        int c = tid + i * 256;
        int row = c >> 3, chk = (c & 7) * 8;
        int gr = q0 + row;
        int grs = (gr < NN) ? gr : 0;
        cp16(qs_u + (uint32_t)(row * KV_STR + chk) * 2u,
             Qp + (size_t)grs * DD + chk, (gr < NN) ? 16 : 0);
    }
    CP_COMMIT();
    issueKV(0, 0); CP_COMMIT();
    issueKV(1, 1); CP_COMMIT();

    cp_wait<2>();                  // Q resident (KV0/KV1 in flight)
    __syncthreads();

    // Q fragments register-resident
    const int lrow = (lane & 7) + ((lane >> 3) & 1) * 8;
    const int lcol = ((lane >> 4) & 1) * 8;
    uint32_t aq[4][4];
    #pragma unroll
    for (int kb = 0; kb < 4; kb++)
        ldsm4(aq[kb],
              qs_u + (uint32_t)((wid * 16 + lrow) * KV_STR + kb * 16 + lcol) * 2u);

    const int krow = (lane & 7) + ((lane >> 4) & 1) * 8;
    const int kcol = ((lane >> 3) & 1) * 8;
    const int vrow = (lane & 7) + ((lane >> 3) & 1) * 8;
    const int vcol = ((lane >> 4) & 1) * 8;

    float o[8][4] = {};
    float l_st[2] = {0.f, 0.f};

    const int NKT = (NN + 63) / 64;   // 10; tiles 0..NKT-2 full, last masked

    auto tile_body = [&](int kt, bool masked) {
        cp_wait<1>();
        __syncthreads();
        if (kt + 2 < NKT) issueKV(kt + 2, (kt + 2) % 3);
        CP_COMMIT();

        const uint32_t ks_u = s_base + (uint32_t)((kt % 3) * KV_STAGE) * 2u;
        const uint32_t vs_u = ks_u + 64 * KV_STR * 2u;

        float s[8][4] = {};
        #pragma unroll
        for (int kb = 0; kb < 4; kb++) {
            #pragma unroll
            for (int ntp = 0; ntp < 4; ntp++) {
                uint32_t bf[4];
                ldsm4(bf, ks_u + (uint32_t)((ntp * 16 + krow) * KV_STR + kb * 16 + kcol) * 2u);
                mma_f16(s[2 * ntp],     aq[kb], bf[0], bf[1], s[2 * ntp]);
                mma_f16(s[2 * ntp + 1], aq[kb], bf[2], bf[3], s[2 * ntp + 1]);
            }
        }

        if (masked) {
            const int kb_tok = kt * 64;
            #pragma unroll
            for (int nt = 0; nt < 8; nt++) {
                int c = kb_tok + nt * 8 + 2 * tid4;
                if (c >= NN)     { s[nt][0] = -1e30f; s[nt][2] = -1e30f; }
                if (c + 1 >= NN) { s[nt][1] = -1e30f; s[nt][3] = -1e30f; }
            }
        }

        #pragma unroll
        for (int nt = 0; nt < 8; nt++) {
            #pragma unroll
            for (int e = 0; e < 4; e++)
                s[nt][e] = ex2(s[nt][e]);
            l_st[0] += s[nt][0] + s[nt][1];
            l_st[1] += s[nt][2] + s[nt][3];
        }

        #pragma unroll
        for (int kk = 0; kk < 4; kk++) {
            uint32_t ap[4];
            ap[0] = packh2(s[2 * kk][0],     s[2 * kk][1]);
            ap[1] = packh2(s[2 * kk][2],     s[2 * kk][3]);
            ap[2] = packh2(s[2 * kk + 1][0], s[2 * kk + 1][1]);
            ap[3] = packh2(s[2 * kk + 1][2], s[2 * kk + 1][3]);
            #pragma unroll
            for (int ntp = 0; ntp < 4; ntp++) {
                uint32_t bf[4];
                ldsm4t(bf, vs_u + (uint32_t)((kk * 16 + vrow) * KV_STR + ntp * 16 + vcol) * 2u);
                mma_f16(o[2 * ntp],     ap, bf[0], bf[1], o[2 * ntp]);
                mma_f16(o[2 * ntp + 1], ap, bf[2], bf[3], o[2 * ntp + 1]);
            }
        }
    };

    for (int kt = 0; kt < NKT - 1; kt++)
        tile_body(kt, false);
    tile_body(NKT - 1, true);        // peeled masked tile

    #pragma unroll
    for (int rr = 0; rr < 2; rr++) {
        l_st[rr] += __shfl_xor_sync(0xffffffffu, l_st[rr], 1);
        l_st[rr] += __shfl_xor_sync(0xffffffffu, l_st[rr], 2);
    }

    #pragma unroll
    for (int rr = 0; rr < 2; rr++) {
        int n = q0 + wid * 16 + grp + rr * 8;
        if (n >= NN) continue;
        float inv_l = 1.0f / l_st[rr];
        #pragma unroll
        for (int nt = 0; nt < 8; nt++) {
            int d0 = nt * 8 + 2 * tid4;
            float e0 = o[nt][2 * rr] * inv_l;
            float e1 = o[nt][2 * rr + 1] * inv_l;
            *(uint32_t*)(g_att + ((size_t)b * NN + n) * CC + h * DD + d0) = packh2(e0, e1);
        }
    }
}

// ---------------------------------------------------------------------------
// Kernel 3: output projection + bias -> d_out (fp32)
// ---------------------------------------------------------------------------
__global__ void __launch_bounds__(128, 3) proj_kernel(
    const float* __restrict__ bias, float* __restrict__ out)
{
    extern __shared__ __half smh[];
    float acc[4][8][4] = {};
    const int m0 = blockIdx.y * 128;
    const int n0 = blockIdx.x * 128;

    gemm_cp(g_att, g_wproj, MTOK, CC, CC, m0, n0, acc, smh);

    const int lane = threadIdx.x & 31;
    const int wid  = threadIdx.x >> 5;
    const int grp  = lane >> 2;
    const int tid4 = lane & 3;
    const int wm   = (wid & 1) * 64;
    const int wn   = (wid >> 1) * 64;

    #pragma unroll
    for (int mt = 0; mt < 4; mt++) {
        #pragma unroll
        for (int rr = 0; rr < 2; rr++) {
            int r = m0 + wm + mt * 16 + grp + rr * 8;
            if (r >= MTOK) continue;
            #pragma unroll
            for (int nt = 0; nt < 8; nt++) {
                int c = n0 + wn + nt * 8 + 2 * tid4;
                float2 ov = make_float2(acc[mt][nt][2 * rr] + bias[c],
                                        acc[mt][nt][2 * rr + 1] + bias[c + 1]);
                *(float2*)(out + (size_t)r * CC + c) = ov;
            }
        }
    }
}

// ---------------------------------------------------------------------------
extern "C" void kernel_launch(void* const* d_in, const int* in_sizes, int n_in,
                              void* d_out, int out_size)
{
    (void)in_sizes; (void)n_in; (void)out_size;
    const float* x      = (const float*)d_in[0];
    const float* w_qkv  = (const float*)d_in[1];
    const float* b_qkv  = (const float*)d_in[2];
    const float* w_proj = (const float*)d_in[3];
    const float* b_proj = (const float*)d_in[4];
    const float* rsin   = (const float*)d_in[5];
    const float* rcos   = (const float*)d_in[6];
    float* out = (float*)d_out;

    cudaFuncSetAttribute(qkv_kernel,  cudaFuncAttributeMaxDynamicSharedMemorySize, GEMM_SMEM_BYTES);
    cudaFuncSetAttribute(proj_kernel, cudaFuncAttributeMaxDynamicSharedMemorySize, GEMM_SMEM_BYTES);
    cudaFuncSetAttribute(attn_kernel, cudaFuncAttributeMaxDynamicSharedMemorySize, ATT_SMEM_BYTES);

    __half* gx;  cudaGetSymbolAddress((void**)&gx,  g_x);
    __half* gwq; cudaGetSymbolAddress((void**)&gwq, g_wqkv);
    __half* gwp; cudaGetSymbolAddress((void**)&gwp, g_wproj);

    int n4x = MTOK * CC / 4;
    int n4q = CC * QKVN / 4;
    int n4p = CC * CC / 4;
    int n4  = n4x + n4q + n4p;
    cvt_all_kernel<<<(n4 + 511) / 512, 512>>>(
        (const float4*)x,      (uint2*)gx,  n4x,
        (const float4*)w_qkv,  (uint2*)gwq, n4q,
        (const float4*)w_proj, (uint2*)gwp, n4p);

    dim3 g1(QKVN / 128, (MTOK + 127) / 128);     // 18 x 145
    qkv_kernel<<<g1, 128, GEMM_SMEM_BYTES>>>(b_qkv, rsin, rcos);

    dim3 g2((NN + 127) / 128, BB * HH);          // 5 x 384
    attn_kernel<<<g2, 256, ATT_SMEM_BYTES>>>();

    dim3 g3(CC / 128, (MTOK + 127) / 128);       // 6 x 145
    proj_kernel<<<g3, 128, GEMM_SMEM_BYTES>>>(b_proj, out);
}

// round 16
// speedup vs baseline: 2.1637x; 1.0012x over previous
#include <cuda_runtime.h>
#include <cuda_fp16.h>
#include <cstdint>

#define BB   32
#define NN   577
#define CC   768
#define HH   12
#define DD   64
#define MTOK (BB*NN)        // 18464
#define QKVN (3*CC)         // 2304

// Scratch (allocation-free rule: __device__ globals) — all fp16
__device__ __half g_Q[(size_t)BB*HH*NN*DD];
__device__ __half g_K[(size_t)BB*HH*NN*DD];
__device__ __half g_V[(size_t)BB*HH*NN*DD];
__device__ __half g_att[(size_t)MTOK*CC];
__device__ __half g_x[(size_t)MTOK*CC];
__device__ __half g_wqkv[(size_t)CC*QKVN];
__device__ __half g_wproj[(size_t)CC*CC];

// ---------------------------------------------------------------------------
// helpers
// ---------------------------------------------------------------------------
__device__ __forceinline__ uint32_t packh2(float a, float b) {
    __half2 h = __floats2half2_rn(a, b);
    return *(uint32_t*)&h;
}
__device__ __forceinline__ float ex2(float x) {
    float r;
    asm("ex2.approx.ftz.f32 %0, %1;" : "=f"(r) : "f"(x));
    return r;
}
__device__ __forceinline__ void ldsm4(uint32_t (&r)[4], uint32_t saddr) {
    asm volatile("ldmatrix.sync.aligned.m8n8.x4.shared.b16 {%0,%1,%2,%3}, [%4];"
        : "=r"(r[0]), "=r"(r[1]), "=r"(r[2]), "=r"(r[3]) : "r"(saddr));
}
__device__ __forceinline__ void ldsm4t(uint32_t (&r)[4], uint32_t saddr) {
    asm volatile("ldmatrix.sync.aligned.m8n8.x4.trans.shared.b16 {%0,%1,%2,%3}, [%4];"
        : "=r"(r[0]), "=r"(r[1]), "=r"(r[2]), "=r"(r[3]) : "r"(saddr));
}
__device__ __forceinline__ void mma_f16(float (&d)[4], const uint32_t (&a)[4],
                                        uint32_t b0, uint32_t b1,
                                        const float (&c)[4]) {
    asm volatile(
        "mma.sync.aligned.m16n8k16.row.col.f32.f16.f16.f32 "
        "{%0,%1,%2,%3}, {%4,%5,%6,%7}, {%8,%9}, {%10,%11,%12,%13};\n"
        : "=f"(d[0]), "=f"(d[1]), "=f"(d[2]), "=f"(d[3])
        : "r"(a[0]), "r"(a[1]), "r"(a[2]), "r"(a[3]),
          "r"(b0), "r"(b1),
          "f"(c[0]), "f"(c[1]), "f"(c[2]), "f"(c[3]));
}
__device__ __forceinline__ void cp16(uint32_t saddr, const void* gptr, int sz) {
    asm volatile("cp.async.cg.shared.global [%0], [%1], 16, %2;\n"
                 :: "r"(saddr), "l"(gptr), "r"(sz));
}
#define CP_COMMIT() asm volatile("cp.async.commit_group;\n")
template<int N> __device__ __forceinline__ void cp_wait() {
    asm volatile("cp.async.wait_group %0;\n" :: "n"(N));
}
__device__ __forceinline__ uint32_t smem_u32(const void* p) {
    uint32_t a;
    asm("{ .reg .u64 t; cvta.to.shared.u64 t, %1; cvt.u32.u64 %0, t; }"
        : "=r"(a) : "l"(p));
    return a;
}

// ---------------------------------------------------------------------------
// Pre-convert: fp32 -> fp16, all three tensors in ONE launch (512 threads)
// ---------------------------------------------------------------------------
__global__ void cvt_all_kernel(const float4* __restrict__ x,   uint2* __restrict__ gx,  int nx,
                               const float4* __restrict__ wq,  uint2* __restrict__ gwq, int nq,
                               const float4* __restrict__ wp,  uint2* __restrict__ gwp, int np)
{
    int i = blockIdx.x * blockDim.x + threadIdx.x;
    const float4* s;
    uint2* d;
    int j = i;
    if (j < nx) { s = x; d = gx; }
    else {
        j -= nx;
        if (j < nq) { s = wq; d = gwq; }
        else {
            j -= nq;
            if (j >= np) return;
            s = wp; d = gwp;
        }
    }
    float4 v = s[j];
    uint2 o;
    o.x = packh2(v.x, v.y);
    o.y = packh2(v.z, v.w);
    d[j] = o;
}

// ---------------------------------------------------------------------------
// fp16 GEMM mainloop: 128x128 block, 4 warps (64x64 each), BK=32, 3-stage
// cp.async, launch_bounds(128,3) = 12 warps/SM. B-fragment double-buffered
// inside the ntp loop so the ldsm4t->MMA scoreboard wait is off the critical
// path (+4 regs only; 64x64 warp tile caps at 170 regs for 3 CTAs).
// ---------------------------------------------------------------------------
#define AS_STR 40
#define BS_STR 136
#define AS_SZ  (128*AS_STR)
#define BS_SZ  (32*BS_STR)
#define STAGE_SZ (AS_SZ + BS_SZ)
#define GEMM_SMEM_BYTES (3*STAGE_SZ*2)  // 56832

__device__ __forceinline__ void gemm_cp(
    const __half* __restrict__ A, const __half* __restrict__ W,
    int M, int Kdim, int Nld, int m0, int n0,
    float (&acc)[4][8][4], __half* __restrict__ sm)
{
    const int tid  = threadIdx.x;
    const int lane = tid & 31;
    const int wid  = tid >> 5;
    const int wm   = (wid & 1) * 64;
    const int wn   = (wid >> 1) * 64;

    const int arow = tid >> 2;
    const int achk = (tid & 3) * 8;
    const int bkr  = tid >> 4;
    const int bnc  = (tid & 15) * 8;

    const int lrow = (lane & 7) + ((lane >> 3) & 1) * 8;
    const int lcol = ((lane >> 4) & 1) * 8;

    const uint32_t s_base = smem_u32(sm);
    const int KT = Kdim / 32;

    auto issue = [&](int t, int buf) {
        int k0 = t * 32;
        uint32_t as = s_base + (uint32_t)(buf * STAGE_SZ) * 2u;
        uint32_t bs = as + AS_SZ * 2u;
        #pragma unroll
        for (int i = 0; i < 4; i++) {
            int row = arow + 32 * i;
            int gr  = m0 + row;
            int grs = (gr < M) ? gr : 0;
            cp16(as + (uint32_t)(row * AS_STR + achk) * 2u,
                 A + (size_t)grs * Kdim + k0 + achk, (gr < M) ? 16 : 0);
        }
        #pragma unroll
        for (int i = 0; i < 4; i++) {
            int kr = bkr + 8 * i;
            cp16(bs + (uint32_t)(kr * BS_STR + bnc) * 2u,
                 W + (size_t)(k0 + kr) * Nld + n0 + bnc, 16);
        }
    };

    issue(0, 0); CP_COMMIT();
    issue(1, 1); CP_COMMIT();

    for (int t = 0; t < KT; t++) {
        cp_wait<1>();
        __syncthreads();
        if (t + 2 < KT) issue(t + 2, (t + 2) % 3);
        CP_COMMIT();

        const uint32_t as = s_base + (uint32_t)((t % 3) * STAGE_SZ) * 2u;
        const uint32_t bs = as + AS_SZ * 2u;

        #pragma unroll
        for (int sub = 0; sub < 2; sub++) {
            uint32_t a[4][4];
            #pragma unroll
            for (int mt = 0; mt < 4; mt++)
                ldsm4(a[mt], as + (uint32_t)((wm + mt * 16 + lrow) * AS_STR
                                             + sub * 16 + lcol) * 2u);
            uint32_t bf[2][4];
            ldsm4t(bf[0], bs + (uint32_t)((sub * 16 + lrow) * BS_STR
                                          + wn + lcol) * 2u);
            #pragma unroll
            for (int ntp = 0; ntp < 4; ntp++) {
                if (ntp < 3)
                    ldsm4t(bf[(ntp + 1) & 1],
                           bs + (uint32_t)((sub * 16 + lrow) * BS_STR
                                           + wn + (ntp + 1) * 16 + lcol) * 2u);
                const uint32_t* bc = bf[ntp & 1];
                #pragma unroll
                for (int mt = 0; mt < 4; mt++) {
                    mma_f16(acc[mt][2 * ntp],     a[mt], bc[0], bc[1], acc[mt][2 * ntp]);
                    mma_f16(acc[mt][2 * ntp + 1], a[mt], bc[2], bc[3], acc[mt][2 * ntp + 1]);
                }
            }
        }
    }
}

// ---------------------------------------------------------------------------
// Kernel 1: QKV GEMM + bias + RoPE + q-scale, scatter fp16 to [B,H,N,D].
// q-scale folds log2(e) so attention softmax can use raw exp2.
// ---------------------------------------------------------------------------
#define QSCALE (0.125f * 1.4426950408889634f)

__global__ void __launch_bounds__(128, 3) qkv_kernel(
    const float* __restrict__ bias,
    const float* __restrict__ rsin, const float* __restrict__ rcos)
{
    extern __shared__ __half smh[];
    float acc[4][8][4] = {};
    const int m0 = blockIdx.y * 128;
    const int n0 = blockIdx.x * 128;

    gemm_cp(g_x, g_wqkv, MTOK, CC, QKVN, m0, n0, acc, smh);

    const int lane = threadIdx.x & 31;
    const int wid  = threadIdx.x >> 5;
    const int grp  = lane >> 2;
    const int tid4 = lane & 3;
    const int wm   = (wid & 1) * 64;
    const int wn   = (wid >> 1) * 64;

    const int which = n0 / CC;
    __half* dst = (which == 0) ? g_Q : ((which == 1) ? g_K : g_V);
    const int h = ((n0 + wn) % CC) / DD;
    const bool is_v = (which == 2);
    const bool is_q = (which == 0);

    #pragma unroll
    for (int nt = 0; nt < 8; nt++) {
        int c = n0 + wn + nt * 8 + 2 * tid4;
        float b0 = bias[c], b1 = bias[c + 1];
        #pragma unroll
        for (int mt = 0; mt < 4; mt++) {
            acc[mt][nt][0] += b0; acc[mt][nt][1] += b1;
            acc[mt][nt][2] += b0; acc[mt][nt][3] += b1;
        }
    }

    #pragma unroll
    for (int mt = 0; mt < 4; mt++) {
        #pragma unroll
        for (int rr = 0; rr < 2; rr++) {
            int m = m0 + wm + mt * 16 + grp + rr * 8;
            if (m >= MTOK) continue;
            int bb = m / NN;
            int n  = m - bb * NN;
            #pragma unroll
            for (int nt = 0; nt < 8; nt++) {
                int d0 = nt * 8 + 2 * tid4;
                float v0 = acc[mt][nt][2 * rr];
                float v1 = acc[mt][nt][2 * rr + 1];
                float o0 = v0, o1 = v1;
                if (!is_v && n > 0) {
                    float p0 = acc[mt][nt ^ 4][2 * rr];
                    float p1 = acc[mt][nt ^ 4][2 * rr + 1];
                    float sgn = (nt < 4) ? -1.f : 1.f;
                    float2 cs = *(const float2*)(rcos + (size_t)(n - 1) * DD + d0);
                    float2 sn = *(const float2*)(rsin + (size_t)(n - 1) * DD + d0);
                    o0 = v0 * cs.x + sgn * p0 * sn.x;
                    o1 = v1 * cs.y + sgn * p1 * sn.y;
                }
                if (is_q) { o0 *= QSCALE; o1 *= QSCALE; }
                *(uint32_t*)(dst + (((size_t)bb * HH + h) * NN + n) * DD + d0) =
                    packh2(o0, o1);
            }
        }
    }
}

// ---------------------------------------------------------------------------
// Kernel 2: flash attention (proven config): 8 warps x 16 q-rows, 3-stage KV,
// one barrier per k-tile, no online max (raw ex2, log2e folded into q),
// l deferred, masked last tile peeled. launch_bounds(256,2) = 16 warps/SM.
// ---------------------------------------------------------------------------
#define KV_STR 72
#define KV_STAGE (2*64*KV_STR)              // 9216 halves
#define QS_OFF (3*KV_STAGE)                 // 27648 halves
#define ATT_SMEM_HALVES (QS_OFF + 128*KV_STR)   // 36864
#define ATT_SMEM_BYTES  (ATT_SMEM_HALVES*2)     // 73728

__global__ void __launch_bounds__(256, 2) attn_kernel()
{
    extern __shared__ __half smh[];

    const int tid  = threadIdx.x;
    const int lane = tid & 31;
    const int wid  = tid >> 5;              // 0..7
    const int grp  = lane >> 2;
    const int tid4 = lane & 3;

    const int q0 = blockIdx.x * 128;
    const int bh = blockIdx.y;
    const int b = bh / HH, h = bh - b * HH;

    const __half* Qp = g_Q + (size_t)bh * NN * DD;
    const __half* Kp = g_K + (size_t)bh * NN * DD;
    const __half* Vp = g_V + (size_t)bh * NN * DD;

    const uint32_t s_base = smem_u32(smh);
    const uint32_t qs_u = s_base + QS_OFF * 2u;

    auto issueKV = [&](int t, int buf) {
        int kb = t * 64;
        uint32_t ks = s_base + (uint32_t)(buf * KV_STAGE) * 2u;
        uint32_t vs = ks + 64 * KV_STR * 2u;
        #pragma unroll
        for (int i = 0; i < 2; i++) {
            int c = tid + i * 256;
            int row = c >> 3, chk = (c & 7) * 8;
            int gr = kb + row;
            int grs = (gr < NN) ? gr : 0;
            int sz = (gr < NN) ? 16 : 0;
            cp16(ks + (uint32_t)(row * KV_STR + chk) * 2u, Kp + (size_t)grs * DD + chk, sz);
            cp16(vs + (uint32_t)(row * KV_STR + chk) * 2u, Vp + (size_t)grs * DD + chk, sz);
        }
    };

    #pragma unroll
    for (int i = 0; i < 4; i++) {
        int c = tid + i * 256;
        int row = c >> 3, chk = (c & 7) * 8;
        int gr = q0 + row;
        int grs = (gr < NN) ? gr : 0;
        cp16(qs_u + (uint32_t)(row * KV_STR + chk) * 2u,
             Qp + (size_t)grs * DD + chk, (gr < NN) ? 16 : 0);
    }
    CP_COMMIT();
    issueKV(0, 0); CP_COMMIT();
    issueKV(1, 1); CP_COMMIT();

    cp_wait<2>();
    __syncthreads();

    const int lrow = (lane & 7) + ((lane >> 3) & 1) * 8;
    const int lcol = ((lane >> 4) & 1) * 8;
    uint32_t aq[4][4];
    #pragma unroll
    for (int kb = 0; kb < 4; kb++)
        ldsm4(aq[kb],
              qs_u + (uint32_t)((wid * 16 + lrow) * KV_STR + kb * 16 + lcol) * 2u);

    const int krow = (lane & 7) + ((lane >> 4) & 1) * 8;
    const int kcol = ((lane >> 3) & 1) * 8;
    const int vrow = (lane & 7) + ((lane >> 3) & 1) * 8;
    const int vcol = ((lane >> 4) & 1) * 8;

    float o[8][4] = {};
    float l_st[2] = {0.f, 0.f};

    const int NKT = (NN + 63) / 64;   // 10

    auto tile_body = [&](int kt, bool masked) {
        cp_wait<1>();
        __syncthreads();
        if (kt + 2 < NKT) issueKV(kt + 2, (kt + 2) % 3);
        CP_COMMIT();

        const uint32_t ks_u = s_base + (uint32_t)((kt % 3) * KV_STAGE) * 2u;
        const uint32_t vs_u = ks_u + 64 * KV_STR * 2u;

        float s[8][4] = {};
        #pragma unroll
        for (int kb = 0; kb < 4; kb++) {
            #pragma unroll
            for (int ntp = 0; ntp < 4; ntp++) {
                uint32_t bf[4];
                ldsm4(bf, ks_u + (uint32_t)((ntp * 16 + krow) * KV_STR + kb * 16 + kcol) * 2u);
                mma_f16(s[2 * ntp],     aq[kb], bf[0], bf[1], s[2 * ntp]);
                mma_f16(s[2 * ntp + 1], aq[kb], bf[2], bf[3], s[2 * ntp + 1]);
            }
        }

        if (masked) {
            const int kb_tok = kt * 64;
            #pragma unroll
            for (int nt = 0; nt < 8; nt++) {
                int c = kb_tok + nt * 8 + 2 * tid4;
                if (c >= NN)     { s[nt][0] = -1e30f; s[nt][2] = -1e30f; }
                if (c + 1 >= NN) { s[nt][1] = -1e30f; s[nt][3] = -1e30f; }
            }
        }

        #pragma unroll
        for (int nt = 0; nt < 8; nt++) {
            #pragma unroll
            for (int e = 0; e < 4; e++)
                s[nt][e] = ex2(s[nt][e]);
            l_st[0] += s[nt][0] + s[nt][1];
            l_st[1] += s[nt][2] + s[nt][3];
        }

        #pragma unroll
        for (int kk = 0; kk < 4; kk++) {
            uint32_t ap[4];
            ap[0] = packh2(s[2 * kk][0],     s[2 * kk][1]);
            ap[1] = packh2(s[2 * kk][2],     s[2 * kk][3]);
            ap[2] = packh2(s[2 * kk + 1][0], s[2 * kk + 1][1]);
            ap[3] = packh2(s[2 * kk + 1][2], s[2 * kk + 1][3]);
            #pragma unroll
            for (int ntp = 0; ntp < 4; ntp++) {
                uint32_t bf[4];
                ldsm4t(bf, vs_u + (uint32_t)((kk * 16 + vrow) * KV_STR + ntp * 16 + vcol) * 2u);
                mma_f16(o[2 * ntp],     ap, bf[0], bf[1], o[2 * ntp]);
                mma_f16(o[2 * ntp + 1], ap, bf[2], bf[3], o[2 * ntp + 1]);
            }
        }
    };

    for (int kt = 0; kt < NKT - 1; kt++)
        tile_body(kt, false);
    tile_body(NKT - 1, true);

    #pragma unroll
    for (int rr = 0; rr < 2; rr++) {
        l_st[rr] += __shfl_xor_sync(0xffffffffu, l_st[rr], 1);
        l_st[rr] += __shfl_xor_sync(0xffffffffu, l_st[rr], 2);
    }

    #pragma unroll
    for (int rr = 0; rr < 2; rr++) {
        int n = q0 + wid * 16 + grp + rr * 8;
        if (n >= NN) continue;
        float inv_l = 1.0f / l_st[rr];
        #pragma unroll
        for (int nt = 0; nt < 8; nt++) {
            int d0 = nt * 8 + 2 * tid4;
            float e0 = o[nt][2 * rr] * inv_l;
            float e1 = o[nt][2 * rr + 1] * inv_l;
            *(uint32_t*)(g_att + ((size_t)b * NN + n) * CC + h * DD + d0) = packh2(e0, e1);
        }
    }
}

// ---------------------------------------------------------------------------
// Kernel 3: output projection + bias -> d_out (fp32)
// ---------------------------------------------------------------------------
__global__ void __launch_bounds__(128, 3) proj_kernel(
    const float* __restrict__ bias, float* __restrict__ out)
{
    extern __shared__ __half smh[];
    float acc[4][8][4] = {};
    const int m0 = blockIdx.y * 128;
    const int n0 = blockIdx.x * 128;

    gemm_cp(g_att, g_wproj, MTOK, CC, CC, m0, n0, acc, smh);

    const int lane = threadIdx.x & 31;
    const int wid  = threadIdx.x >> 5;
    const int grp  = lane >> 2;
    const int tid4 = lane & 3;
    const int wm   = (wid & 1) * 64;
    const int wn   = (wid >> 1) * 64;

    #pragma unroll
    for (int mt = 0; mt < 4; mt++) {
        #pragma unroll
        for (int rr = 0; rr < 2; rr++) {
            int r = m0 + wm + mt * 16 + grp + rr * 8;
            if (r >= MTOK) continue;
            #pragma unroll
            for (int nt = 0; nt < 8; nt++) {
                int c = n0 + wn + nt * 8 + 2 * tid4;
                float2 ov = make_float2(acc[mt][nt][2 * rr] + bias[c],
                                        acc[mt][nt][2 * rr + 1] + bias[c + 1]);
                *(float2*)(out + (size_t)r * CC + c) = ov;
            }
        }
    }
}

// ---------------------------------------------------------------------------
extern "C" void kernel_launch(void* const* d_in, const int* in_sizes, int n_in,
                              void* d_out, int out_size)
{
    (void)in_sizes; (void)n_in; (void)out_size;
    const float* x      = (const float*)d_in[0];
    const float* w_qkv  = (const float*)d_in[1];
    const float* b_qkv  = (const float*)d_in[2];
    const float* w_proj = (const float*)d_in[3];
    const float* b_proj = (const float*)d_in[4];
    const float* rsin   = (const float*)d_in[5];
    const float* rcos   = (const float*)d_in[6];
    float* out = (float*)d_out;

    cudaFuncSetAttribute(qkv_kernel,  cudaFuncAttributeMaxDynamicSharedMemorySize, GEMM_SMEM_BYTES);
    cudaFuncSetAttribute(proj_kernel, cudaFuncAttributeMaxDynamicSharedMemorySize, GEMM_SMEM_BYTES);
    cudaFuncSetAttribute(attn_kernel, cudaFuncAttributeMaxDynamicSharedMemorySize, ATT_SMEM_BYTES);

    __half* gx;  cudaGetSymbolAddress((void**)&gx,  g_x);
    __half* gwq; cudaGetSymbolAddress((void**)&gwq, g_wqkv);
    __half* gwp; cudaGetSymbolAddress((void**)&gwp, g_wproj);

    int n4x = MTOK * CC / 4;
    int n4q = CC * QKVN / 4;
    int n4p = CC * CC / 4;
    int n4  = n4x + n4q + n4p;
    cvt_all_kernel<<<(n4 + 511) / 512, 512>>>(
        (const float4*)x,      (uint2*)gx,  n4x,
        (const float4*)w_qkv,  (uint2*)gwq, n4q,
        (const float4*)w_proj, (uint2*)gwp, n4p);

    dim3 g1(QKVN / 128, (MTOK + 127) / 128);     // 18 x 145
    qkv_kernel<<<g1, 128, GEMM_SMEM_BYTES>>>(b_qkv, rsin, rcos);

    dim3 g2((NN + 127) / 128, BB * HH);          // 5 x 384
    attn_kernel<<<g2, 256, ATT_SMEM_BYTES>>>();

    dim3 g3(CC / 128, (MTOK + 127) / 128);       // 6 x 145
    proj_kernel<<<g3, 128, GEMM_SMEM_BYTES>>>(b_proj, out);
}